// round 7
// baseline (speedup 1.0000x reference)
#include <cuda_runtime.h>
#include <cuda_bf16.h>
#include <cstdint>

// u_quant_weight_linear: out[o,i] = clip(rint(w[o,i]/s), -qmax, qmax) * s
//   s = max(alh[o], 1e-5); b = rint(clip(|bit[o]|,1,6)); qmax = max(2^(b-1)-1,1)
//
// R7: bulk-async (TMA/UBLKCP) pipeline. The LDG path saturates at ~6 TB/s
// across all occ/MLP configs; test whether cp.async.bulk -> smem bypasses it.
// 296 CTAs (2/SM, one wave), 512 thr, 4-stage x 16KB ring, issue depth 3.
// Segments strided by grid (11008 segs -> 37/38 per CTA, near-perfect balance).
// Each 1024-float4 segment spans <=2 rows (1024 < 2752) -> two-row select.

#define NTHR        512
#define GRID        296
#define SEG_F4      1024                 // float4 per segment
#define SEG_BYTES   (SEG_F4 * 16)        // 16384
#define NSEG        11008                // 11272192 / 1024
#define STAGES      4
#define VEC_PER_ROW 2752u
#define LAST_ROW    4095u

__device__ __forceinline__ void make_params(const float* __restrict__ alh,
                                            const float* __restrict__ bit,
                                            unsigned r, float& s, float& qmax)
{
    s = fmaxf(alh[r], 1e-5f);
    const float b = rintf(fminf(fmaxf(fabsf(bit[r]), 1.0f), 6.0f));
    qmax = fmaxf(exp2f(b - 1.0f) - 1.0f, 1.0f);
}

__device__ __forceinline__ float4 quant4(float4 v, float s, float qmax)
{
    const float qmin = -qmax;
    // True IEEE divide: rint decisions must match the reference exactly.
    v.x = fminf(fmaxf(rintf(v.x / s), qmin), qmax) * s;
    v.y = fminf(fmaxf(rintf(v.y / s), qmin), qmax) * s;
    v.z = fminf(fmaxf(rintf(v.z / s), qmin), qmax) * s;
    v.w = fminf(fmaxf(rintf(v.w / s), qmin), qmax) * s;
    return v;
}

__device__ __forceinline__ void mbar_init(uint32_t mbar, uint32_t count)
{
    asm volatile("mbarrier.init.shared.b64 [%0], %1;" :: "r"(mbar), "r"(count) : "memory");
}

__device__ __forceinline__ void bulk_load(uint32_t dst_smem, const void* src,
                                          uint32_t bytes, uint32_t mbar)
{
    asm volatile(
        "mbarrier.arrive.expect_tx.shared.b64 _, [%0], %1;" :: "r"(mbar), "r"(bytes) : "memory");
    asm volatile(
        "cp.async.bulk.shared::cta.global.mbarrier::complete_tx::bytes [%0], [%1], %2, [%3];"
        :: "r"(dst_smem), "l"(src), "r"(bytes), "r"(mbar) : "memory");
}

__device__ __forceinline__ void mbar_wait(uint32_t mbar, uint32_t parity)
{
    asm volatile(
        "{\n\t"
        ".reg .pred p;\n\t"
        "WL_%=:\n\t"
        "mbarrier.try_wait.parity.acquire.cta.shared::cta.b64 p, [%0], %1, 0x989680;\n\t"
        "@p bra WD_%=;\n\t"
        "bra WL_%=;\n\t"
        "WD_%=:\n\t"
        "}"
        :: "r"(mbar), "r"(parity) : "memory");
}

__global__ __launch_bounds__(NTHR, 2)
void fake_quant_kernel(const float4* __restrict__ w,
                       const float*  __restrict__ alh,
                       const float*  __restrict__ bit,
                       float4* __restrict__ out)
{
    extern __shared__ float4 stage_buf[];            // STAGES * SEG_F4
    __shared__ __align__(8) uint64_t mbar[STAGES];

    const int tid = threadIdx.x;
    const int bid = blockIdx.x;

    const uint32_t smem_base =
        (uint32_t)__cvta_generic_to_shared(stage_buf);
    const uint32_t mbar_base =
        (uint32_t)__cvta_generic_to_shared(mbar);

    if (tid == 0) {
        #pragma unroll
        for (int s = 0; s < STAGES; s++) mbar_init(mbar_base + s * 8, 1);
    }
    __syncthreads();

    // This CTA's segment count: segs are bid, bid+GRID, bid+2*GRID, ...
    const int n = (NSEG - bid + GRID - 1) / GRID;    // 37 or 38

    // Prologue: fill 3 stages.
    if (tid == 0) {
        #pragma unroll
        for (int k = 0; k < 3; k++) {
            if (k < n) {
                const unsigned seg = bid + (unsigned)k * GRID;
                bulk_load(smem_base + (k % STAGES) * SEG_BYTES,
                          w + (size_t)seg * SEG_F4, SEG_BYTES,
                          mbar_base + (k % STAGES) * 8);
            }
        }
    }

    for (int k = 0; k < n; k++) {
        // Issue load k+3 into stage (k+3)%4 — that stage was consumed at
        // iteration k-1 and all threads passed its trailing __syncthreads().
        if (tid == 0 && k + 3 < n) {
            const int kk = k + 3;
            const unsigned seg = bid + (unsigned)kk * GRID;
            bulk_load(smem_base + (kk % STAGES) * SEG_BYTES,
                      w + (size_t)seg * SEG_F4, SEG_BYTES,
                      mbar_base + (kk % STAGES) * 8);
        }

        const int st = k % STAGES;
        mbar_wait(mbar_base + st * 8, (unsigned)(k / STAGES) & 1);

        // Per-segment two-row params (segment spans at most 2 rows).
        const unsigned seg  = bid + (unsigned)k * GRID;
        const unsigned base = seg * SEG_F4;
        const unsigned r0   = base / VEC_PER_ROW;
        const unsigned boundary = (r0 + 1u) * VEC_PER_ROW;
        const unsigned r1   = min(r0 + 1u, LAST_ROW);
        float s0, q0, s1, q1;
        make_params(alh, bit, r0, s0, q0);
        make_params(alh, bit, r1, s1, q1);

        const float4* sp = stage_buf + st * SEG_F4;
        #pragma unroll
        for (int i = 0; i < SEG_F4 / NTHR; i++) {     // 2 per thread
            const unsigned li  = tid + i * NTHR;
            const unsigned idx = base + li;
            float4 v = sp[li];
            const bool hi = idx >= boundary;
            __stcs(&out[idx], quant4(v, hi ? s1 : s0, hi ? q1 : q0));
        }
        __syncthreads();   // stage consumed by all threads before reissue
    }
}

extern "C" void kernel_launch(void* const* d_in, const int* in_sizes, int n_in,
                              void* d_out, int out_size)
{
    const float4* w   = (const float4*)d_in[0];  // weight [4096, 11008]
    const float*  alh = (const float*)d_in[1];   // [4096, 1]
    const float*  bit = (const float*)d_in[2];   // [4096, 1]
    float4* out = (float4*)d_out;

    const int smem = STAGES * SEG_BYTES;         // 64 KB dynamic
    cudaFuncSetAttribute(fake_quant_kernel,
                         cudaFuncAttributeMaxDynamicSharedMemorySize, smem);
    fake_quant_kernel<<<GRID, NTHR, smem>>>(w, alh, bit, out);
}

// round 8
// speedup vs baseline: 1.1107x; 1.1107x over previous
#include <cuda_runtime.h>
#include <cuda_bf16.h>
#include <cstdint>

// u_quant_weight_linear: out[o,i] = clip(rint(w[o,i]/s), -qmax, qmax) * s
//   s = max(alh[o], 1e-5); b = rint(clip(|bit[o]|,1,6)); qmax = max(2^(b-1)-1,1)
//
// R8: single-variable change vs R5 (best, 6.05 TB/s): 256-bit global ld/st
// (Blackwell LDG.E.256 / STG.E.256 via ld.global.v8.f32). Same bytes per
// thread (4 x 32B front-batched), half the LDG/STG instruction count ->
// halves LSU dispatch-queue pressure. Grid/layout identical to R5:
// total vec8 = 4096*1376 = 5636096 = 5504 * 1024; 5504 blocks x 256 thr
// x 4 items, zero tail. 1376 % 32 == 0 -> row index warp-uniform.

#define VEC8_PER_ROW 1376u
#define LAST_ROW     4095u
#define NTHR         256
#define BATCH        4
#define CHUNK        (NTHR * BATCH)          // 1024 vec8
#define NBLK         5504                     // 5504*1024 = 5636096 exactly

struct f8 { float4 a, b; };

__device__ __forceinline__ f8 ldg256_cs(const float* p)
{
    f8 r;
    asm volatile("ld.global.cs.v8.f32 {%0,%1,%2,%3,%4,%5,%6,%7}, [%8];"
                 : "=f"(r.a.x), "=f"(r.a.y), "=f"(r.a.z), "=f"(r.a.w),
                   "=f"(r.b.x), "=f"(r.b.y), "=f"(r.b.z), "=f"(r.b.w)
                 : "l"(p));
    return r;
}

__device__ __forceinline__ void stg256_cs(float* p, f8 v)
{
    asm volatile("st.global.cs.v8.f32 [%0], {%1,%2,%3,%4,%5,%6,%7,%8};"
                 :: "l"(p),
                    "f"(v.a.x), "f"(v.a.y), "f"(v.a.z), "f"(v.a.w),
                    "f"(v.b.x), "f"(v.b.y), "f"(v.b.z), "f"(v.b.w)
                 : "memory");
}

__device__ __forceinline__ void row_params(unsigned idx8,
                                           const float* __restrict__ alh,
                                           const float* __restrict__ bit,
                                           float& s, float& qmax)
{
    const unsigned r = idx8 / VEC8_PER_ROW;   // warp-uniform (1376 % 32 == 0)
    s = fmaxf(alh[r], 1e-5f);
    const float b = rintf(fminf(fmaxf(fabsf(bit[r]), 1.0f), 6.0f));
    qmax = fmaxf(exp2f(b - 1.0f) - 1.0f, 1.0f);
}

__device__ __forceinline__ float qf(float x, float s, float qmin, float qmax)
{
    // True IEEE divide: rint decisions must match the reference exactly.
    return fminf(fmaxf(rintf(x / s), qmin), qmax) * s;
}

__device__ __forceinline__ f8 quant8(f8 v, float s, float qmax)
{
    const float qmin = -qmax;
    v.a.x = qf(v.a.x, s, qmin, qmax);  v.a.y = qf(v.a.y, s, qmin, qmax);
    v.a.z = qf(v.a.z, s, qmin, qmax);  v.a.w = qf(v.a.w, s, qmin, qmax);
    v.b.x = qf(v.b.x, s, qmin, qmax);  v.b.y = qf(v.b.y, s, qmin, qmax);
    v.b.z = qf(v.b.z, s, qmin, qmax);  v.b.w = qf(v.b.w, s, qmin, qmax);
    return v;
}

__global__ __launch_bounds__(NTHR, 5)
void fake_quant_kernel(const float* __restrict__ w,
                       const float* __restrict__ alh,
                       const float* __restrict__ bit,
                       float* __restrict__ out)
{
    const unsigned base = blockIdx.x * CHUNK + threadIdx.x;   // vec8 index

    // Front-batch all 4 256-bit loads.
    f8 v[BATCH];
    #pragma unroll
    for (int i = 0; i < BATCH; i++)
        v[i] = ldg256_cs(w + (size_t)(base + i * NTHR) * 8u);

    #pragma unroll
    for (int i = 0; i < BATCH; i++) {
        const unsigned idx8 = base + i * NTHR;
        float s, qmax;
        row_params(idx8, alh, bit, s, qmax);
        stg256_cs(out + (size_t)idx8 * 8u, quant8(v[i], s, qmax));
    }
}

extern "C" void kernel_launch(void* const* d_in, const int* in_sizes, int n_in,
                              void* d_out, int out_size)
{
    const float* w   = (const float*)d_in[0];  // weight [4096, 11008]
    const float* alh = (const float*)d_in[1];  // [4096, 1]
    const float* bit = (const float*)d_in[2];  // [4096, 1]
    float* out = (float*)d_out;

    fake_quant_kernel<<<NBLK, NTHR>>>(w, alh, bit, out);
}